// round 15
// baseline (speedup 1.0000x reference)
#include <cuda_runtime.h>
#include <cuda_fp16.h>
#include <math.h>

#define BATCH 8
#define CH 64
#define PLANE 50176            /* 224*224 */
#define NTPB 1568              /* 32px tiles per batch */
#define NTILES (BATCH*NTPB)    /* 12544 */
#define POOLED_ELEMS 4194304
#define NB_RED 8
#define NB_INNER 512
#define NB_FILL 4096

// ---------------- device scratch ----------------
__device__ __half g_xTh[(size_t)BATCH*PLANE*CH];  // [B][pix][C] fp16
__device__ float  g_part[(size_t)NTILES*CH];      // per-tile channel partials
__device__ float  g_lohi[16];
__device__ float  g_cval[BATCH*CH];
__device__ float2 g_polar[8192];                  // (logr, a/pi - 1)
__device__ int    g_ready[BATCH];                 // per-batch lo/hi-ready flags

// ---- K1: transpose + partials; block0 polar, block1 cval, block2 reset --
__global__ void __launch_bounds__(256) k_T(const float* __restrict__ x,
                                           const float* __restrict__ l) {
    __shared__ float tile[CH][33];
    int bx   = blockIdx.x;
    int b    = bx / NTPB;
    int tidx = bx - b * NTPB;
    int t0   = tidx * 32;
    int tid  = threadIdx.x;

    const float4* xp = (const float4*)(x + (size_t)b * CH * PLANE);
    int base4 = t0 >> 2;
#pragma unroll
    for (int it = 0; it < 2; it++) {
        int p    = it * 256 + tid;
        int c    = p >> 3;
        int col4 = p & 7;
        float4 v = xp[(size_t)c * (PLANE / 4) + base4 + col4];
        tile[c][col4*4+0] = v.x; tile[c][col4*4+1] = v.y;
        tile[c][col4*4+2] = v.z; tile[c][col4*4+3] = v.w;
    }
    __syncthreads();

    if (tid < CH) {
        float s = 0.f;
#pragma unroll
        for (int k = 0; k < 32; k++) s += tile[tid][k];
        g_part[((size_t)b * NTPB + tidx) * CH + tid] = s;
    }

    int rr = tid >> 3, q = tid & 7;
    half2 h0 = __floats2half2_rn(tile[8*q+0][rr], tile[8*q+1][rr]);
    half2 h1 = __floats2half2_rn(tile[8*q+2][rr], tile[8*q+3][rr]);
    half2 h2 = __floats2half2_rn(tile[8*q+4][rr], tile[8*q+5][rr]);
    half2 h3 = __floats2half2_rn(tile[8*q+6][rr], tile[8*q+7][rr]);
    uint4 u;
    u.x = *(unsigned int*)&h0; u.y = *(unsigned int*)&h1;
    u.z = *(unsigned int*)&h2; u.w = *(unsigned int*)&h3;
    ((uint4*)g_xTh)[((size_t)b * PLANE + t0 + rr) * 8 + q] = u;

    if (bx == 0) {       // polar table (data-independent, plain stores)
        for (int e = tid; e < 8192; e += 256) {
            int i = e >> 7, j = e & 127;
            float xg = (i - 32) * (1.f / 32.f);
            float yg = (j - 64) * (1.f / 64.f);
            float logr = logf(fmaxf(sqrtf(xg*xg + yg*yg), 1e-12f));
            float a = atan2f(yg, xg);
            if (!(a > 0.f)) a += 6.283185307179586f;
            g_polar[e] = make_float2(logr, a * 0.3183098861837907f - 1.f);
        }
    } else if (bx == 1) {   // constant-region bilinear values (x + l only)
#pragma unroll
        for (int rep = 0; rep < 2; rep++) {
            int idx = rep * 256 + tid;      // (bb, c)
            int bb = idx >> 6;
            float gx = l[2*bb], gy = l[2*bb + 1];
            float ix = fminf(fmaxf((gx + 1.f) * 112.f - 0.5f, 0.f), 223.f);
            float iy = fminf(fmaxf((gy + 1.f) * 112.f - 0.5f, 0.f), 223.f);
            float x0f = floorf(ix), y0f = floorf(iy);
            float wx = ix - x0f, wy = iy - y0f;
            int x0 = (int)x0f, y0 = (int)y0f;
            int x1 = min(x0 + 1, 223), y1 = min(y0 + 1, 223);
            const float* pp = x + (size_t)idx * PLANE;
            g_cval[idx] = pp[y0*224 + x0] * (1.f-wx) * (1.f-wy)
                        + pp[y0*224 + x1] * wx * (1.f-wy)
                        + pp[y1*224 + x0] * (1.f-wx) * wy
                        + pp[y1*224 + x1] * wx * wy;
        }
    } else if (bx == 2) {   // reset ready flags for this call (pre-k_fused)
        if (tid < BATCH) g_ready[tid] = 0;
    }
}

// ---- K2: reducers + gather + fill in one launch -------------------------
__global__ void __launch_bounds__(256) k_fused(
        const float* __restrict__ l,
        const float* __restrict__ w1, const float* __restrict__ b1,
        const float* __restrict__ w2, const float* __restrict__ b2,
        float* __restrict__ outw, float* __restrict__ out) {
    int tid = threadIdx.x;

    // ============ role A: per-batch reduce + MLP (bids 0..7) ============
    if (blockIdx.x < NB_RED) {
        __shared__ float4 red4[16][17];
        __shared__ float br[CH];
        __shared__ float hid[32];
        __shared__ float wgt[2];
        int b = blockIdx.x;
        {   // 16 groups x 98 tiles, unrolled float4 accumulate
            int c4 = tid & 15, grp = tid >> 4;
            const float4* p4 = (const float4*)g_part;
            size_t base = ((size_t)b * NTPB + grp * 98) * 16 + c4;
            float4 a = make_float4(0.f, 0.f, 0.f, 0.f);
#pragma unroll
            for (int t = 0; t < 98; t++) {
                float4 v = __ldg(&p4[base + (size_t)t * 16]);
                a.x += v.x; a.y += v.y; a.z += v.z; a.w += v.w;
            }
            red4[grp][c4] = a;
        }
        __syncthreads();
        if (tid < 16) {
            float4 s = make_float4(0.f, 0.f, 0.f, 0.f);
#pragma unroll
            for (int g = 0; g < 16; g++) {
                float4 v = red4[g][tid];
                s.x += v.x; s.y += v.y; s.z += v.z; s.w += v.w;
            }
            const float inv = 1.f / (float)PLANE;
            br[4*tid+0] = s.x * inv; br[4*tid+1] = s.y * inv;
            br[4*tid+2] = s.z * inv; br[4*tid+3] = s.w * inv;
        }
        __syncthreads();
        if (tid < 32) {
            float acc = b1[tid];
#pragma unroll
            for (int cc = 0; cc < 64; cc++) acc += br[cc] * w1[cc * 32 + tid];
            hid[tid] = fmaxf(acc, 0.f);
        }
        __syncthreads();
        if (tid < 2) {
            float acc = b2[tid];
#pragma unroll
            for (int m = 0; m < 32; m++) acc += hid[m] * w2[m * 2 + tid];
            float wv = 1.f / (1.f + expf(-acc));
            wgt[tid] = wv;
            outw[2 * b + tid] = wv;
        }
        __syncthreads();
        if (tid == 0) {
            g_lohi[2*b + 0] = logf(wgt[0] * 0.01f);
            g_lohi[2*b + 1] = logf(wgt[1] * 0.60f);
            __threadfence();                 // order lo/hi before flag
            atomicExch(&g_ready[b], 1);
        }
        return;
    }

    // ============ role C: constant fill (bids 520..4615) ================
    if (blockIdx.x >= NB_RED + NB_INNER) {
        int idx = (blockIdx.x - NB_RED - NB_INNER) * 256 + tid;  // float4 idx
        int plane = idx >> 11;
        int rem = idx & 2047;
        int h = rem >> 5, w4 = rem & 31;
        if (h < 16 && w4 < 8) return;
        float v = g_cval[plane];
        __stcs(&((float4*)out)[idx], make_float4(v, v, v, v));
        return;
    }

    // ============ role B: gather (bids 8..519) ==========================
    __shared__ float st[8][68];
    int gblk   = blockIdx.x - NB_RED;
    int warpId = tid >> 5;
    int lane   = tid & 31;
    int wpos   = gblk * 8 + warpId;
    int b   = wpos >> 9;
    int pos = wpos & 511;
    int h = pos >> 5, w = pos & 31;
    int tap = lane >> 3, c8 = lane & 7;

    // wait for this batch's lo/hi (L2 reads; producers ordered by fence)
    if (tid == 0) {
        while (__ldcg(&g_ready[b]) == 0) __nanosleep(64);
    }
    __syncthreads();

    float l0 = l[2*b], l1 = l[2*b + 1];
    float lo = __ldcg(&g_lohi[2*b]), hi = __ldcg(&g_lohi[2*b + 1]);
    float inv2 = 2.f / (hi - lo);

    int s16 = lane & 15;
    int i = 4 * h + (s16 >> 2);
    int j = 4 * w + (s16 & 3);
    float2 pb = g_polar[(i << 7) | j];
    float gx = pb.y + l0;
    float gy = (pb.x - lo) * inv2 - 1.f + l1;
    float ix = fminf(fmaxf((gx + 1.f) * 112.f - 0.5f, 0.f), 223.f);
    float iy = fminf(fmaxf((gy + 1.f) * 112.f - 0.5f, 0.f), 223.f);

    const uint4* xt = (const uint4*)g_xTh;
    size_t bbase = (size_t)b * PLANE * 8;
    float acc[8];
#pragma unroll
    for (int k = 0; k < 8; k++) acc[k] = 0.f;

#pragma unroll
    for (int s = 0; s < 16; s++) {
        float ixs = __shfl_sync(0xffffffffu, ix, s);
        float iys = __shfl_sync(0xffffffffu, iy, s);
        float x0f = floorf(ixs), y0f = floorf(iys);
        float wx = ixs - x0f, wy = iys - y0f;
        int x0 = (int)x0f, y0 = (int)y0f;
        int x1 = min(x0 + 1, 223), y1 = min(y0 + 1, 223);
        int xs = (tap & 1) ? x1 : x0;
        int ys = (tap & 2) ? y1 : y0;
        float wt = ((tap & 1) ? wx : 1.f - wx) * ((tap & 2) ? wy : 1.f - wy);
        uint4 v = xt[bbase + (size_t)(ys * 224 + xs) * 8 + c8];
        half2* hp = (half2*)&v;
        float2 f0 = __half22float2(hp[0]);
        float2 f1 = __half22float2(hp[1]);
        float2 f2 = __half22float2(hp[2]);
        float2 f3 = __half22float2(hp[3]);
        acc[0] += wt * f0.x;  acc[1] += wt * f0.y;
        acc[2] += wt * f1.x;  acc[3] += wt * f1.y;
        acc[4] += wt * f2.x;  acc[5] += wt * f2.y;
        acc[6] += wt * f3.x;  acc[7] += wt * f3.y;
    }
#pragma unroll
    for (int k = 0; k < 8; k++) {
        acc[k] += __shfl_xor_sync(0xffffffffu, acc[k], 8);
        acc[k] += __shfl_xor_sync(0xffffffffu, acc[k], 16);
    }
    if (tap == 0) {
#pragma unroll
        for (int k = 0; k < 8; k++)
            st[warpId][8 * c8 + k] = acc[k] * (1.f / 16.f);
    }
    __syncthreads();

    if (tid < 64) {
        int c = tid;
        int bpos = gblk * 8;
        int bB = bpos >> 9;
        int p0 = bpos & 511;
        int hB = p0 >> 5, w0 = p0 & 31;
        float4 v0 = make_float4(st[0][c], st[1][c], st[2][c], st[3][c]);
        float4 v1 = make_float4(st[4][c], st[5][c], st[6][c], st[7][c]);
        size_t ob = (((size_t)(bB * CH + c) * 64 + hB) * 128 + w0);
        *(float4*)(out + ob)     = v0;
        *(float4*)(out + ob + 4) = v1;
    }
}

// ---------------------------------------------------------------------
extern "C" void kernel_launch(void* const* d_in, const int* in_sizes, int n_in,
                              void* d_out, int out_size) {
    const float* x  = (const float*)d_in[0];
    const float* l  = (const float*)d_in[1];
    const float* w1 = (const float*)d_in[2];
    const float* b1 = (const float*)d_in[3];
    const float* w2 = (const float*)d_in[4];
    const float* b2 = (const float*)d_in[5];
    float* out  = (float*)d_out;
    float* outw = out + POOLED_ELEMS;

    k_T<<<NTILES, 256>>>(x, l);
    k_fused<<<NB_RED + NB_INNER + NB_FILL, 256>>>(l, w1, b1, w2, b2, outw, out);
}

// round 16
// speedup vs baseline: 1.1450x; 1.1450x over previous
#include <cuda_runtime.h>
#include <cuda_fp16.h>
#include <math.h>

#define BATCH 8
#define CH 64
#define PLANE 50176            /* 224*224 */
#define NTPB 1568              /* 32px tiles per batch */
#define NTILES (BATCH*NTPB)    /* 12544 */
#define POOLED_ELEMS 4194304
#define NB_RED1 128            /* 16 per batch */
#define NB_RED2 8
#define NB_FILL 4096
#define NB_INNER 512
#define FILL0 (NB_RED1 + NB_RED2)              /* 136 */
#define GATH0 (FILL0 + NB_FILL)                /* 4232 */
#define NBLK  (GATH0 + NB_INNER)               /* 4744 */

// ---------------- device scratch ----------------
__device__ __half g_xTh[(size_t)BATCH*PLANE*CH];  // [B][pix][C] fp16
__device__ float  g_part[(size_t)NTILES*CH];      // per-tile channel partials
__device__ float  g_part2[BATCH*16*CH];           // stage-1 partials
__device__ float  g_lohi[16];
__device__ float  g_cval[BATCH*CH];
__device__ float2 g_polar[8192];                  // (logr, a/pi - 1)
__device__ int    g_done1[BATCH];                 // stage-1 completion counters
__device__ int    g_ready[BATCH];                 // lo/hi-ready flags

// ---- K1: transpose + partials; block0 polar, block1 cval, block2 reset --
__global__ void __launch_bounds__(256) k_T(const float* __restrict__ x,
                                           const float* __restrict__ l) {
    __shared__ float tile[CH][33];
    int bx   = blockIdx.x;
    int b    = bx / NTPB;
    int tidx = bx - b * NTPB;
    int t0   = tidx * 32;
    int tid  = threadIdx.x;

    const float4* xp = (const float4*)(x + (size_t)b * CH * PLANE);
    int base4 = t0 >> 2;
#pragma unroll
    for (int it = 0; it < 2; it++) {
        int p    = it * 256 + tid;
        int c    = p >> 3;
        int col4 = p & 7;
        float4 v = xp[(size_t)c * (PLANE / 4) + base4 + col4];
        tile[c][col4*4+0] = v.x; tile[c][col4*4+1] = v.y;
        tile[c][col4*4+2] = v.z; tile[c][col4*4+3] = v.w;
    }
    __syncthreads();

    if (tid < CH) {
        float s = 0.f;
#pragma unroll
        for (int k = 0; k < 32; k++) s += tile[tid][k];
        g_part[((size_t)b * NTPB + tidx) * CH + tid] = s;
    }

    int rr = tid >> 3, q = tid & 7;
    half2 h0 = __floats2half2_rn(tile[8*q+0][rr], tile[8*q+1][rr]);
    half2 h1 = __floats2half2_rn(tile[8*q+2][rr], tile[8*q+3][rr]);
    half2 h2 = __floats2half2_rn(tile[8*q+4][rr], tile[8*q+5][rr]);
    half2 h3 = __floats2half2_rn(tile[8*q+6][rr], tile[8*q+7][rr]);
    uint4 u;
    u.x = *(unsigned int*)&h0; u.y = *(unsigned int*)&h1;
    u.z = *(unsigned int*)&h2; u.w = *(unsigned int*)&h3;
    ((uint4*)g_xTh)[((size_t)b * PLANE + t0 + rr) * 8 + q] = u;

    if (bx == 0) {       // polar table (data-independent, plain stores)
        for (int e = tid; e < 8192; e += 256) {
            int i = e >> 7, j = e & 127;
            float xg = (i - 32) * (1.f / 32.f);
            float yg = (j - 64) * (1.f / 64.f);
            float logr = logf(fmaxf(sqrtf(xg*xg + yg*yg), 1e-12f));
            float a = atan2f(yg, xg);
            if (!(a > 0.f)) a += 6.283185307179586f;
            g_polar[e] = make_float2(logr, a * 0.3183098861837907f - 1.f);
        }
    } else if (bx == 1) {   // constant-region bilinear values (x + l only)
#pragma unroll
        for (int rep = 0; rep < 2; rep++) {
            int idx = rep * 256 + tid;      // (bb, c)
            int bb = idx >> 6;
            float gx = l[2*bb], gy = l[2*bb + 1];
            float ix = fminf(fmaxf((gx + 1.f) * 112.f - 0.5f, 0.f), 223.f);
            float iy = fminf(fmaxf((gy + 1.f) * 112.f - 0.5f, 0.f), 223.f);
            float x0f = floorf(ix), y0f = floorf(iy);
            float wx = ix - x0f, wy = iy - y0f;
            int x0 = (int)x0f, y0 = (int)y0f;
            int x1 = min(x0 + 1, 223), y1 = min(y0 + 1, 223);
            const float* pp = x + (size_t)idx * PLANE;
            g_cval[idx] = pp[y0*224 + x0] * (1.f-wx) * (1.f-wy)
                        + pp[y0*224 + x1] * wx * (1.f-wy)
                        + pp[y1*224 + x0] * (1.f-wx) * wy
                        + pp[y1*224 + x1] * wx * wy;
        }
    } else if (bx == 2) {   // reset flags/counters for the next k_fused
        if (tid < BATCH) { g_done1[tid] = 0; g_ready[tid] = 0; }
    }
}

// ---- K2: red1 + red2/MLP + fill + gather, ordered by bid ----------------
__global__ void __launch_bounds__(256) k_fused(
        const float* __restrict__ l,
        const float* __restrict__ w1, const float* __restrict__ b1,
        const float* __restrict__ w2, const float* __restrict__ b2,
        float* __restrict__ outw, float* __restrict__ out) {
    int tid = threadIdx.x;

    // ===== stage-1 reduce: 128 blocks, 16 per batch (bids 0..127) =======
    if (blockIdx.x < NB_RED1) {
        __shared__ float4 s4[16][17];
        int r = blockIdx.x;
        int b = r >> 4, seg = r & 15;
        int c4 = tid & 15, sub = tid >> 4;          // 16 subs x 16 quads
        const float4* p4 = (const float4*)g_part;
        float4 a = make_float4(0.f, 0.f, 0.f, 0.f);
#pragma unroll
        for (int k = 0; k < 7; k++) {               // 16 subs x 7 >= 98
            int t = sub * 7 + k;
            if (t < 98) {
                float4 v = p4[((size_t)b * NTPB + seg * 98 + t) * 16 + c4];
                a.x += v.x; a.y += v.y; a.z += v.z; a.w += v.w;
            }
        }
        s4[sub][c4] = a;
        __syncthreads();
        if (tid < 16) {
            float4 s = make_float4(0.f, 0.f, 0.f, 0.f);
#pragma unroll
            for (int g = 0; g < 16; g++) {
                float4 v = s4[g][tid];
                s.x += v.x; s.y += v.y; s.z += v.z; s.w += v.w;
            }
            ((float4*)g_part2)[(b * 16 + seg) * 16 + tid] = s;
        }
        __threadfence();
        __syncthreads();
        if (tid == 0) atomicAdd(&g_done1[b], 1);
        return;
    }

    // ===== stage-2 reduce + MLP: 8 blocks (bids 128..135) ===============
    if (blockIdx.x < FILL0) {
        __shared__ float sm[256];
        __shared__ float br[CH];
        __shared__ float hid[32];
        __shared__ float wgt[2];
        int b = blockIdx.x - NB_RED1;
        if (tid == 0) {
            while (__ldcg(&g_done1[b]) != 16) __nanosleep(64);
        }
        __syncthreads();
        __threadfence();
        {
            int c = tid & 63, g4 = tid >> 6;        // 4 groups x 4 segs
            float s = 0.f;
#pragma unroll
            for (int k = 0; k < 4; k++)
                s += __ldcg(&g_part2[(b * 16 + g4 * 4 + k) * 64 + c]);
            sm[tid] = s;
        }
        __syncthreads();
        if (tid < 64)
            br[tid] = (sm[tid] + sm[tid+64] + sm[tid+128] + sm[tid+192])
                      * (1.f / (float)PLANE);
        __syncthreads();
        if (tid < 32) {
            float acc = b1[tid];
#pragma unroll
            for (int cc = 0; cc < 64; cc++) acc += br[cc] * w1[cc * 32 + tid];
            hid[tid] = fmaxf(acc, 0.f);
        }
        __syncthreads();
        if (tid < 2) {
            float acc = b2[tid];
#pragma unroll
            for (int m = 0; m < 32; m++) acc += hid[m] * w2[m * 2 + tid];
            float wv = 1.f / (1.f + expf(-acc));
            wgt[tid] = wv;
            outw[2 * b + tid] = wv;
        }
        __syncthreads();
        if (tid == 0) {
            g_lohi[2*b + 0] = logf(wgt[0] * 0.01f);
            g_lohi[2*b + 1] = logf(wgt[1] * 0.60f);
            __threadfence();
            atomicExch(&g_ready[b], 1);
        }
        return;
    }

    // ===== fill: 4096 blocks (bids 136..4231) ===========================
    if (blockIdx.x < GATH0) {
        int idx = (blockIdx.x - FILL0) * 256 + tid;  // float4 index
        int plane = idx >> 11;
        int rem = idx & 2047;
        int h = rem >> 5, w4 = rem & 31;
        if (h < 16 && w4 < 8) return;
        float v = g_cval[plane];
        __stcs(&((float4*)out)[idx], make_float4(v, v, v, v));
        return;
    }

    // ===== gather: 512 blocks (bids 4232..4743, dispatch last) ==========
    __shared__ float st[8][68];
    int gblk   = blockIdx.x - GATH0;
    int warpId = tid >> 5;
    int lane   = tid & 31;
    int wpos   = gblk * 8 + warpId;
    int b   = wpos >> 9;
    int pos = wpos & 511;
    int h = pos >> 5, w = pos & 31;
    int tap = lane >> 3, c8 = lane & 7;

    if (tid == 0) {
        while (__ldcg(&g_ready[b]) == 0) __nanosleep(64);
    }
    __syncthreads();

    float l0 = l[2*b], l1 = l[2*b + 1];
    float lo = __ldcg(&g_lohi[2*b]), hi = __ldcg(&g_lohi[2*b + 1]);
    float inv2 = 2.f / (hi - lo);

    int s16 = lane & 15;
    int i = 4 * h + (s16 >> 2);
    int j = 4 * w + (s16 & 3);
    float2 pb = g_polar[(i << 7) | j];
    float gx = pb.y + l0;
    float gy = (pb.x - lo) * inv2 - 1.f + l1;
    float ix = fminf(fmaxf((gx + 1.f) * 112.f - 0.5f, 0.f), 223.f);
    float iy = fminf(fmaxf((gy + 1.f) * 112.f - 0.5f, 0.f), 223.f);

    const uint4* xt = (const uint4*)g_xTh;
    size_t bbase = (size_t)b * PLANE * 8;
    float acc[8];
#pragma unroll
    for (int k = 0; k < 8; k++) acc[k] = 0.f;

#pragma unroll
    for (int s = 0; s < 16; s++) {
        float ixs = __shfl_sync(0xffffffffu, ix, s);
        float iys = __shfl_sync(0xffffffffu, iy, s);
        float x0f = floorf(ixs), y0f = floorf(iys);
        float wx = ixs - x0f, wy = iys - y0f;
        int x0 = (int)x0f, y0 = (int)y0f;
        int x1 = min(x0 + 1, 223), y1 = min(y0 + 1, 223);
        int xs = (tap & 1) ? x1 : x0;
        int ys = (tap & 2) ? y1 : y0;
        float wt = ((tap & 1) ? wx : 1.f - wx) * ((tap & 2) ? wy : 1.f - wy);
        uint4 v = xt[bbase + (size_t)(ys * 224 + xs) * 8 + c8];
        half2* hp = (half2*)&v;
        float2 f0 = __half22float2(hp[0]);
        float2 f1 = __half22float2(hp[1]);
        float2 f2 = __half22float2(hp[2]);
        float2 f3 = __half22float2(hp[3]);
        acc[0] += wt * f0.x;  acc[1] += wt * f0.y;
        acc[2] += wt * f1.x;  acc[3] += wt * f1.y;
        acc[4] += wt * f2.x;  acc[5] += wt * f2.y;
        acc[6] += wt * f3.x;  acc[7] += wt * f3.y;
    }
#pragma unroll
    for (int k = 0; k < 8; k++) {
        acc[k] += __shfl_xor_sync(0xffffffffu, acc[k], 8);
        acc[k] += __shfl_xor_sync(0xffffffffu, acc[k], 16);
    }
    if (tap == 0) {
#pragma unroll
        for (int k = 0; k < 8; k++)
            st[warpId][8 * c8 + k] = acc[k] * (1.f / 16.f);
    }
    __syncthreads();

    if (tid < 64) {
        int c = tid;
        int bpos = gblk * 8;
        int bB = bpos >> 9;
        int p0 = bpos & 511;
        int hB = p0 >> 5, w0 = p0 & 31;
        float4 v0 = make_float4(st[0][c], st[1][c], st[2][c], st[3][c]);
        float4 v1 = make_float4(st[4][c], st[5][c], st[6][c], st[7][c]);
        size_t ob = (((size_t)(bB * CH + c) * 64 + hB) * 128 + w0);
        *(float4*)(out + ob)     = v0;
        *(float4*)(out + ob + 4) = v1;
    }
}

// ---------------------------------------------------------------------
extern "C" void kernel_launch(void* const* d_in, const int* in_sizes, int n_in,
                              void* d_out, int out_size) {
    const float* x  = (const float*)d_in[0];
    const float* l  = (const float*)d_in[1];
    const float* w1 = (const float*)d_in[2];
    const float* b1 = (const float*)d_in[3];
    const float* w2 = (const float*)d_in[4];
    const float* b2 = (const float*)d_in[5];
    float* out  = (float*)d_out;
    float* outw = out + POOLED_ELEMS;

    k_T<<<NTILES, 256>>>(x, l);
    k_fused<<<NBLK, 256>>>(l, w1, b1, w2, b2, outw, out);
}